// round 2
// baseline (speedup 1.0000x reference)
#include <cuda_runtime.h>
#include <math_constants.h>

#define NS     5000
#define SPTS   10
#define NSEG   9
#define KNN    20
#define HH     512
#define WW     512
#define HC     102
#define WC     102
#define NCELL  (HC*WC)

// ---------------- scratch (static device globals; no runtime allocation) ----
__device__ float  g_pts[NS * SPTS * 2];     // bezier points, (x,y) pairs per stroke
__device__ float4 g_colw[NS];               // rgb + width packed
__device__ int    g_tidx[NCELL * KNN];      // per coarse cell: sorted top-K stroke ids
__device__ float  g_tw[NCELL * KNN];        // per coarse cell: width of slot-k stroke

// ---------------- kernel 1: bezier points + color/width packing -------------
// Matches XLA rounding: each HLO op individually rounded, no FMA contraction.
// t = linspace(0,1,10) = fl(i * fl(1/9)) (endpoint rounds to exactly 1.0).
__global__ void k_bezier(const float* __restrict__ cs, const float* __restrict__ ce,
                         const float* __restrict__ cc, const float* __restrict__ color,
                         const float* __restrict__ loc, const float* __restrict__ width)
{
    int n = blockIdx.x * blockDim.x + threadIdx.x;
    if (n >= NS) return;
    float lx = loc[2*n], ly = loc[2*n+1];
    float Sx = __fadd_rn(cs[2*n],   lx), Sy = __fadd_rn(cs[2*n+1], ly);
    float Ex = __fadd_rn(ce[2*n],   lx), Ey = __fadd_rn(ce[2*n+1], ly);
    float Cx = __fadd_rn(cc[2*n],   lx), Cy = __fadd_rn(cc[2*n+1], ly);
    float dsx = __fsub_rn(Sx, Cx), dsy = __fsub_rn(Sy, Cy);
    float dex = __fsub_rn(Ex, Cx), dey = __fsub_rn(Ey, Cy);
    float step = __fdiv_rn(1.0f, 9.0f);
    #pragma unroll
    for (int i = 0; i < SPTS; i++) {
        float t   = __fmul_rn((float)i, step);
        float omt = __fsub_rn(1.0f, t);
        float o2  = __fmul_rn(omt, omt);
        float t2  = __fmul_rn(t, t);
        // pts = (c + omt2*(s-c)) + t2*(e-c), left-to-right, no fma
        float px = __fadd_rn(__fadd_rn(Cx, __fmul_rn(o2, dsx)), __fmul_rn(t2, dex));
        float py = __fadd_rn(__fadd_rn(Cy, __fmul_rn(o2, dsy)), __fmul_rn(t2, dey));
        g_pts[(n*SPTS + i)*2 + 0] = px;
        g_pts[(n*SPTS + i)*2 + 1] = py;
    }
    g_colw[n] = make_float4(color[3*n], color[3*n+1], color[3*n+2], width[n]);
}

// ---------------- kernel 2: coarse-grid top-K nearest strokes ---------------
// One thread per coarse cell. Ascending-sorted insertion list; strict '<'
// reproduces jax.lax.top_k stable tie ordering. Distances use the exact
// reference rounding (sub, mul, mul, add — no fma) so the selected SET and
// ORDER match bit-for-bit.
#define TILE2 1024
__global__ void k_topk(const float* __restrict__ loc, const float* __restrict__ width)
{
    __shared__ float2 sl[TILE2];
    int cell = blockIdx.x * blockDim.x + threadIdx.x;
    bool active = (cell < NCELL);
    float px = 0.f, py = 0.f;
    if (active) {
        int ci = cell / WC, cj = cell % WC;
        float step = __fdiv_rn(512.0f, 101.0f);   // linspace(0,512,102)
        px = __fmul_rn((float)ci, step);
        py = __fmul_rn((float)cj, step);
    }
    float bd[KNN]; int bi[KNN];
    #pragma unroll
    for (int k = 0; k < KNN; k++) { bd[k] = CUDART_INF_F; bi[k] = 0; }

    for (int base = 0; base < NS; base += TILE2) {
        int cnt = min(TILE2, NS - base);
        __syncthreads();
        for (int i = threadIdx.x; i < cnt; i += blockDim.x)
            sl[i] = ((const float2*)loc)[base + i];
        __syncthreads();
        if (active) {
            #pragma unroll 4
            for (int i = 0; i < cnt; i++) {
                float dx = __fsub_rn(px, sl[i].x);
                float dy = __fsub_rn(py, sl[i].y);
                float d  = __fadd_rn(__fmul_rn(dx, dx), __fmul_rn(dy, dy));
                if (d < bd[KNN-1]) {
                    int j = KNN - 1;
                    while (j > 0 && d < bd[j-1]) {
                        bd[j] = bd[j-1]; bi[j] = bi[j-1]; j--;
                    }
                    bd[j] = d; bi[j] = base + i;
                }
            }
        }
    }
    if (active) {
        #pragma unroll
        for (int k = 0; k < KNN; k++) {
            g_tidx[cell*KNN + k] = bi[k];
            g_tw  [cell*KNN + k] = __ldg(width + bi[k]);
        }
    }
}

// ---------------- kernel 3: full-res shading --------------------------------
// 256 threads/block; warp covers an 8x4 pixel tile so lanes mostly share a
// coarse cell (L1 broadcast). The amplified path (segment distance -> r)
// replicates XLA's per-op rounding exactly.
__global__ void __launch_bounds__(256, 2) k_render(float* __restrict__ out)
{
    int lane = threadIdx.x & 31;
    int wrp  = threadIdx.x >> 5;       // 0..7
    int subx = lane & 7, suby = lane >> 3;
    int wx = wrp & 1,  wy = wrp >> 1;
    int w = blockIdx.x * 16 + wx * 8 + subx;   // width index (second coord)
    int h = blockIdx.y * 16 + wy * 4 + suby;   // height index (first coord)

    float stepf = __fdiv_rn(512.0f, 511.0f);   // linspace(0,512,512)
    float pxf = __fmul_rn((float)h, stepf);
    float pyf = __fmul_rn((float)w, stepf);

    // nearest-upsample coarse cell (exact: 102/512 = 51/256 exact in f32)
    int ch = min((int)((float)h * 0.19921875f), HC - 1);
    int cw = min((int)((float)w * 0.19921875f), WC - 1);
    const int* idxp = g_tidx + (ch*WC + cw) * KNN;

    // half-pixel bilinear for the width resize (edge-clamped lerp ==
    // jax's renormalized triangle kernel at the borders); smooth path.
    float yc = ((float)h + 0.5f) * 0.19921875f - 0.5f;
    float xc = ((float)w + 0.5f) * 0.19921875f - 0.5f;
    float y0f = floorf(yc), x0f = floorf(xc);
    float fy = yc - y0f,    fx = xc - x0f;
    int y0 = max(0, min(HC-1, (int)y0f));
    int y1 = max(0, min(HC-1, (int)y0f + 1));
    int x0 = max(0, min(WC-1, (int)x0f));
    int x1 = max(0, min(WC-1, (int)x0f + 1));
    const float* pw00 = g_tw + (y0*WC + x0) * KNN;
    const float* pw01 = g_tw + (y0*WC + x1) * KNN;
    const float* pw10 = g_tw + (y1*WC + x0) * KNN;
    const float* pw11 = g_tw + (y1*WC + x1) * KNN;
    float c00 = (1.f-fy)*(1.f-fx), c01 = (1.f-fy)*fx;
    float c10 = fy*(1.f-fx),       c11 = fy*fx;

    float M = -CUDART_INF_F;
    float sum = 0.f, a0 = 0.f, a1 = 0.f, a2 = 0.f, bw = 0.f;
    float D = CUDART_INF_F;

    #pragma unroll
    for (int k = 0; k < KNN; k++) {
        int idx = __ldg(idxp + k);
        float wk = c00*__ldg(pw00+k) + c01*__ldg(pw01+k)
                 + c10*__ldg(pw10+k) + c11*__ldg(pw11+k);

        const float4* pp = (const float4*)(g_pts + idx * (SPTS*2));
        float4 q0 = __ldg(pp+0), q1 = __ldg(pp+1), q2 = __ldg(pp+2),
               q3 = __ldg(pp+3), q4 = __ldg(pp+4);
        float ptx[SPTS] = {q0.x,q0.z,q1.x,q1.z,q2.x,q2.z,q3.x,q3.z,q4.x,q4.z};
        float pty[SPTS] = {q0.y,q0.w,q1.y,q1.w,q2.y,q2.w,q3.y,q3.w,q4.y,q4.w};

        // m = min over segments of ||P - (a + t*(b-a))||^2, rounded per-op
        // exactly like the reference (no fma, IEEE div).
        float m = CUDART_INF_F;
        #pragma unroll
        for (int s = 0; s < NSEG; s++) {
            float ax = ptx[s],  ay = pty[s];
            float bx = __fsub_rn(ptx[s+1], ax);
            float by = __fsub_rn(pty[s+1], ay);
            float pax = __fsub_rn(pxf, ax);
            float pay = __fsub_rn(pyf, ay);
            float dot1 = __fadd_rn(__fmul_rn(bx, pax), __fmul_rn(by, pay));
            float dot2 = __fadd_rn(__fmul_rn(bx, bx), __fmul_rn(by, by));
            float t = __fdiv_rn(dot1, dot2);
            t = fminf(fmaxf(t, 0.0f), 1.0f);
            float cx = __fadd_rn(ax, __fmul_rn(t, bx));
            float cy = __fadd_rn(ay, __fmul_rn(t, by));
            float dx = __fsub_rn(pxf, cx);
            float dy = __fsub_rn(pyf, cy);
            float d = __fadd_rn(__fmul_rn(dx, dx), __fmul_rn(dy, dy));
            m = fminf(m, d);
        }
        D = fminf(D, m);

        // r = 100000 * (1 / (1e-8 + m)) — reference rounding
        float r = __fmul_rn(100000.0f, __fdiv_rn(1.0f, __fadd_rn(1e-8f, m)));

        float4 col = __ldg(&g_colw[idx]);
        float e;
        if (r > M) {
            float sc = expf(M - r);   // exp(-inf)=0 on first iteration
            sum *= sc; a0 *= sc; a1 *= sc; a2 *= sc; bw *= sc;
            M = r; e = 1.0f;
        } else {
            e = expf(__fsub_rn(r, M));
        }
        sum += e;
        a0 += e * col.x; a1 += e * col.y; a2 += e * col.z;
        bw += e * wk;
    }

    float inv  = __fdiv_rn(1.0f, sum);
    float bs   = bw * inv;
    // XLA lowers jax.nn.sigmoid (lax.logistic) as 0.5 + 0.5*tanh(0.5*x)
    float marg = __fmul_rn(0.5f, __fsub_rn(bs, D));
    float mask = __fadd_rn(0.5f, __fmul_rn(0.5f, tanhf(marg)));
    float om   = __fsub_rn(1.0f, mask);
    int o = (h * WW + w) * 3;
    out[o+0] = __fadd_rn(__fmul_rn(a0*inv, mask), __fmul_rn(om, 0.5f));
    out[o+1] = __fadd_rn(__fmul_rn(a1*inv, mask), __fmul_rn(om, 0.5f));
    out[o+2] = __fadd_rn(__fmul_rn(a2*inv, mask), __fmul_rn(om, 0.5f));
}

// ---------------- launch ----------------------------------------------------
extern "C" void kernel_launch(void* const* d_in, const int* in_sizes, int n_in,
                              void* d_out, int out_size)
{
    const float* curve_s  = (const float*)d_in[0];
    const float* curve_e  = (const float*)d_in[1];
    const float* curve_c  = (const float*)d_in[2];
    const float* color    = (const float*)d_in[3];
    const float* location = (const float*)d_in[4];
    const float* width    = (const float*)d_in[5];
    float* out = (float*)d_out;

    k_bezier<<<(NS + 255) / 256, 256>>>(curve_s, curve_e, curve_c, color, location, width);
    k_topk<<<(NCELL + 63) / 64, 64>>>(location, width);
    dim3 grid(WW / 16, HH / 16);
    k_render<<<grid, 256>>>(out);
}